// round 6
// baseline (speedup 1.0000x reference)
#include <cuda_runtime.h>
#include <cstdint>

// GraphReversePool: out[b, v] = x[b, v2c[v]]
//   x   : [BATCH, N_CLUSTERS] fp32   (d_in[0])
//   v2c : [VERTICES] int32           (d_in[1])
//   out : [BATCH, VERTICES] fp32
//
// R6: tail-quantization fix. 2048 CTAs: CTA pair (2b, 2b+1) handles batch
// row b, each gathering one half of the vertex range. Wave count 3.46 -> 6.92,
// tail waste 13% -> ~1%. The pair's duplicate 100 KB row DMA hits L2
// (adjacent bids co-scheduled; x fits L2). Staging stays one cp.async.bulk.

#define BLOCK_THREADS 1024

__device__ __forceinline__ uint32_t smem_u32(const void* p) {
    return (uint32_t)__cvta_generic_to_shared(p);
}

__global__ __launch_bounds__(BLOCK_THREADS, 2)
void graph_reverse_pool_kernel(const float* __restrict__ x,
                               const int*   __restrict__ v2c,
                               float*       __restrict__ out,
                               int batch, int n_clusters, int n_vertices)
{
    extern __shared__ __align__(16) unsigned char smem_raw[];
    float* srow = reinterpret_cast<float*>(smem_raw);

    const int b    = blockIdx.x >> 1;      // batch row
    const int half = blockIdx.x & 1;       // which vertex half

    const int row_bytes = n_clusters * 4;
    const int mbar_off  = (row_bytes + 15) & ~15;
    uint64_t* mbar = reinterpret_cast<uint64_t*>(smem_raw + mbar_off);
    const uint32_t mbar_addr = smem_u32(mbar);

    const float* __restrict__ xrow = x + (size_t)b * n_clusters;

    const bool can_bulk = ((row_bytes & 15) == 0) &&
                          ((((uintptr_t)xrow) & 15) == 0);

    if (can_bulk) {
        if (threadIdx.x == 0) {
            asm volatile("mbarrier.init.shared.b64 [%0], 1;"
                         :: "r"(mbar_addr) : "memory");
            asm volatile("fence.proxy.async.shared::cta;" ::: "memory");
        }
        __syncthreads();
        if (threadIdx.x == 0) {
            asm volatile("mbarrier.arrive.expect_tx.shared.b64 _, [%0], %1;"
                         :: "r"(mbar_addr), "r"((uint32_t)row_bytes) : "memory");
            asm volatile("cp.async.bulk.shared::cta.global.mbarrier::complete_tx::bytes "
                         "[%0], [%1], %2, [%3];"
                         :: "r"(smem_u32(srow)), "l"(xrow),
                            "r"((uint32_t)row_bytes), "r"(mbar_addr)
                         : "memory");
        }
        uint32_t done = 0;
        while (!done) {
            asm volatile(
                "{\n\t.reg .pred p;\n\t"
                "mbarrier.try_wait.parity.acquire.cta.shared::cta.b64 p, [%1], 0, 0x989680;\n\t"
                "selp.b32 %0, 1, 0, p;\n\t}"
                : "=r"(done) : "r"(mbar_addr) : "memory");
        }
    } else {
        for (int i = threadIdx.x; i < n_clusters; i += BLOCK_THREADS)
            srow[i] = xrow[i];
        __syncthreads();
    }

    // ---- Gather over this CTA's vertex half ----
    const int nv4   = n_vertices >> 2;             // 25000 (exact for 100000)
    const int hbeg  = half ? (nv4 >> 1) : 0;       // quad range [hbeg, hend)
    const int hend  = half ? nv4 : (nv4 >> 1);

    const int4* __restrict__ v2c4 = reinterpret_cast<const int4*>(v2c);
    float4* __restrict__ o = reinterpret_cast<float4*>(out + (size_t)b * n_vertices);

    const int S = BLOCK_THREADS;
    int v = hbeg + threadIdx.x;
    while (v + S < hend) {
        const int4 c0 = v2c4[v];
        const int4 c1 = v2c4[v + S];
        float4 a0, a1;
        a0.x = srow[c0.x]; a0.y = srow[c0.y]; a0.z = srow[c0.z]; a0.w = srow[c0.w];
        a1.x = srow[c1.x]; a1.y = srow[c1.y]; a1.z = srow[c1.z]; a1.w = srow[c1.w];
        __stcs(&o[v],     a0);
        __stcs(&o[v + S], a1);
        v += 2 * S;
    }
    if (v < hend) {
        const int4 c = v2c4[v];
        float4 a;
        a.x = srow[c.x]; a.y = srow[c.y]; a.z = srow[c.z]; a.w = srow[c.w];
        __stcs(&o[v], a);
    }
    // scalar vertex tail (only CTA half==1 handles it; dead for 100000)
    if (half) {
        for (int t = (nv4 << 2) + threadIdx.x; t < n_vertices; t += BLOCK_THREADS) {
            out[(size_t)b * n_vertices + t] = srow[v2c[t]];
        }
    }
}

extern "C" void kernel_launch(void* const* d_in, const int* in_sizes, int n_in,
                              void* d_out, int out_size)
{
    const float* x   = (const float*)d_in[0];
    const int*   v2c = (const int*)  d_in[1];
    float*       out = (float*)d_out;

    const int n_vertices = in_sizes[1];                  // 100000
    const int batch      = out_size / n_vertices;        // 1024
    const int n_clusters = in_sizes[0] / batch;          // 25000

    const int row_bytes  = n_clusters * (int)sizeof(float);      // 100000
    const int smem_bytes = ((row_bytes + 15) & ~15) + 16;        // row + mbarrier

    static bool attr_set = false;
    if (!attr_set) {
        cudaFuncSetAttribute(graph_reverse_pool_kernel,
                             cudaFuncAttributeMaxDynamicSharedMemorySize,
                             smem_bytes);
        attr_set = true;
    }

    graph_reverse_pool_kernel<<<batch * 2, BLOCK_THREADS, smem_bytes>>>(
        x, v2c, out, batch, n_clusters, n_vertices);
}

// round 7
// speedup vs baseline: 1.0018x; 1.0018x over previous
#include <cuda_runtime.h>
#include <cstdint>

// GraphReversePool: out[b, v] = x[b, v2c[v]]
//   x   : [BATCH, N_CLUSTERS] fp32   (d_in[0])
//   v2c : [VERTICES] int32           (d_in[1])
//   out : [BATCH, VERTICES] fp32
//
// R6: tail-quantization fix. 2048 CTAs: CTA pair (2b, 2b+1) handles batch
// row b, each gathering one half of the vertex range. Wave count 3.46 -> 6.92,
// tail waste 13% -> ~1%. The pair's duplicate 100 KB row DMA hits L2
// (adjacent bids co-scheduled; x fits L2). Staging stays one cp.async.bulk.

#define BLOCK_THREADS 1024

__device__ __forceinline__ uint32_t smem_u32(const void* p) {
    return (uint32_t)__cvta_generic_to_shared(p);
}

__global__ __launch_bounds__(BLOCK_THREADS, 2)
void graph_reverse_pool_kernel(const float* __restrict__ x,
                               const int*   __restrict__ v2c,
                               float*       __restrict__ out,
                               int batch, int n_clusters, int n_vertices)
{
    extern __shared__ __align__(16) unsigned char smem_raw[];
    float* srow = reinterpret_cast<float*>(smem_raw);

    const int b    = blockIdx.x >> 1;      // batch row
    const int half = blockIdx.x & 1;       // which vertex half

    const int row_bytes = n_clusters * 4;
    const int mbar_off  = (row_bytes + 15) & ~15;
    uint64_t* mbar = reinterpret_cast<uint64_t*>(smem_raw + mbar_off);
    const uint32_t mbar_addr = smem_u32(mbar);

    const float* __restrict__ xrow = x + (size_t)b * n_clusters;

    const bool can_bulk = ((row_bytes & 15) == 0) &&
                          ((((uintptr_t)xrow) & 15) == 0);

    if (can_bulk) {
        if (threadIdx.x == 0) {
            asm volatile("mbarrier.init.shared.b64 [%0], 1;"
                         :: "r"(mbar_addr) : "memory");
            asm volatile("fence.proxy.async.shared::cta;" ::: "memory");
        }
        __syncthreads();
        if (threadIdx.x == 0) {
            asm volatile("mbarrier.arrive.expect_tx.shared.b64 _, [%0], %1;"
                         :: "r"(mbar_addr), "r"((uint32_t)row_bytes) : "memory");
            asm volatile("cp.async.bulk.shared::cta.global.mbarrier::complete_tx::bytes "
                         "[%0], [%1], %2, [%3];"
                         :: "r"(smem_u32(srow)), "l"(xrow),
                            "r"((uint32_t)row_bytes), "r"(mbar_addr)
                         : "memory");
        }
        uint32_t done = 0;
        while (!done) {
            asm volatile(
                "{\n\t.reg .pred p;\n\t"
                "mbarrier.try_wait.parity.acquire.cta.shared::cta.b64 p, [%1], 0, 0x989680;\n\t"
                "selp.b32 %0, 1, 0, p;\n\t}"
                : "=r"(done) : "r"(mbar_addr) : "memory");
        }
    } else {
        for (int i = threadIdx.x; i < n_clusters; i += BLOCK_THREADS)
            srow[i] = xrow[i];
        __syncthreads();
    }

    // ---- Gather over this CTA's vertex half ----
    const int nv4   = n_vertices >> 2;             // 25000 (exact for 100000)
    const int hbeg  = half ? (nv4 >> 1) : 0;       // quad range [hbeg, hend)
    const int hend  = half ? nv4 : (nv4 >> 1);

    const int4* __restrict__ v2c4 = reinterpret_cast<const int4*>(v2c);
    float4* __restrict__ o = reinterpret_cast<float4*>(out + (size_t)b * n_vertices);

    const int S = BLOCK_THREADS;
    int v = hbeg + threadIdx.x;
    while (v + S < hend) {
        const int4 c0 = v2c4[v];
        const int4 c1 = v2c4[v + S];
        float4 a0, a1;
        a0.x = srow[c0.x]; a0.y = srow[c0.y]; a0.z = srow[c0.z]; a0.w = srow[c0.w];
        a1.x = srow[c1.x]; a1.y = srow[c1.y]; a1.z = srow[c1.z]; a1.w = srow[c1.w];
        __stcs(&o[v],     a0);
        __stcs(&o[v + S], a1);
        v += 2 * S;
    }
    if (v < hend) {
        const int4 c = v2c4[v];
        float4 a;
        a.x = srow[c.x]; a.y = srow[c.y]; a.z = srow[c.z]; a.w = srow[c.w];
        __stcs(&o[v], a);
    }
    // scalar vertex tail (only CTA half==1 handles it; dead for 100000)
    if (half) {
        for (int t = (nv4 << 2) + threadIdx.x; t < n_vertices; t += BLOCK_THREADS) {
            out[(size_t)b * n_vertices + t] = srow[v2c[t]];
        }
    }
}

extern "C" void kernel_launch(void* const* d_in, const int* in_sizes, int n_in,
                              void* d_out, int out_size)
{
    const float* x   = (const float*)d_in[0];
    const int*   v2c = (const int*)  d_in[1];
    float*       out = (float*)d_out;

    const int n_vertices = in_sizes[1];                  // 100000
    const int batch      = out_size / n_vertices;        // 1024
    const int n_clusters = in_sizes[0] / batch;          // 25000

    const int row_bytes  = n_clusters * (int)sizeof(float);      // 100000
    const int smem_bytes = ((row_bytes + 15) & ~15) + 16;        // row + mbarrier

    static bool attr_set = false;
    if (!attr_set) {
        cudaFuncSetAttribute(graph_reverse_pool_kernel,
                             cudaFuncAttributeMaxDynamicSharedMemorySize,
                             smem_bytes);
        attr_set = true;
    }

    graph_reverse_pool_kernel<<<batch * 2, BLOCK_THREADS, smem_bytes>>>(
        x, v2c, out, batch, n_clusters, n_vertices);
}

// round 8
// speedup vs baseline: 1.0827x; 1.0807x over previous
#include <cuda_runtime.h>
#include <cstdint>

// GraphReversePool: out[b, v] = x[b, v2c[v]]
//   x   : [BATCH, N_CLUSTERS] fp32   (d_in[0])
//   v2c : [VERTICES] int32           (d_in[1])
//   out : [BATCH, VERTICES] fp32
//
// R7: R5 structure (1 row / CTA, bulk-DMA staging, 2 CTAs/SM) + surgical
// tail fix: split only enough rows into vertex-halves to make grid an exact
// multiple of the chip's CTA slots (2 * numSMs). Full-row CTAs get low bids
// (scheduled first); short half-row CTAs pack the final wave.
// Extra staging traffic: only (G-1024) * 100 KB (~19 MB), vs R6's +100 MB.

#define BLOCK_THREADS 1024

__device__ __forceinline__ uint32_t smem_u32(const void* p) {
    return (uint32_t)__cvta_generic_to_shared(p);
}

__global__ __launch_bounds__(BLOCK_THREADS, 2)
void graph_reverse_pool_kernel(const float* __restrict__ x,
                               const int*   __restrict__ v2c,
                               float*       __restrict__ out,
                               int batch, int n_clusters, int n_vertices,
                               int n_full)   // bids [0,n_full) = full rows; rest = half rows
{
    extern __shared__ __align__(16) unsigned char smem_raw[];
    float* srow = reinterpret_cast<float*>(smem_raw);

    // ---- map bid -> (batch row, vertex quad range) ----
    int b, half_id;
    const int bid = blockIdx.x;
    if (bid < n_full) {
        b = bid;
        half_id = -1;                       // full vertex range
    } else {
        const int j = bid - n_full;
        b = n_full + (j >> 1);
        half_id = j & 1;
    }

    const int row_bytes = n_clusters * 4;
    const int mbar_off  = (row_bytes + 15) & ~15;
    uint64_t* mbar = reinterpret_cast<uint64_t*>(smem_raw + mbar_off);
    const uint32_t mbar_addr = smem_u32(mbar);

    const float* __restrict__ xrow = x + (size_t)b * n_clusters;

    const bool can_bulk = ((row_bytes & 15) == 0) &&
                          ((((uintptr_t)xrow) & 15) == 0);

    if (can_bulk) {
        if (threadIdx.x == 0) {
            asm volatile("mbarrier.init.shared.b64 [%0], 1;"
                         :: "r"(mbar_addr) : "memory");
            asm volatile("fence.proxy.async.shared::cta;" ::: "memory");
        }
        __syncthreads();
        if (threadIdx.x == 0) {
            asm volatile("mbarrier.arrive.expect_tx.shared.b64 _, [%0], %1;"
                         :: "r"(mbar_addr), "r"((uint32_t)row_bytes) : "memory");
            asm volatile("cp.async.bulk.shared::cta.global.mbarrier::complete_tx::bytes "
                         "[%0], [%1], %2, [%3];"
                         :: "r"(smem_u32(srow)), "l"(xrow),
                            "r"((uint32_t)row_bytes), "r"(mbar_addr)
                         : "memory");
        }
        uint32_t done = 0;
        while (!done) {
            asm volatile(
                "{\n\t.reg .pred p;\n\t"
                "mbarrier.try_wait.parity.acquire.cta.shared::cta.b64 p, [%1], 0, 0x989680;\n\t"
                "selp.b32 %0, 1, 0, p;\n\t}"
                : "=r"(done) : "r"(mbar_addr) : "memory");
        }
    } else {
        for (int i = threadIdx.x; i < n_clusters; i += BLOCK_THREADS)
            srow[i] = xrow[i];
        __syncthreads();
    }

    // ---- Gather over this CTA's quad range ----
    const int nv4 = n_vertices >> 2;               // 25000 (exact for 100000)
    int qbeg, qend;
    if (half_id < 0)      { qbeg = 0;         qend = nv4; }
    else if (half_id == 0){ qbeg = 0;         qend = nv4 >> 1; }
    else                  { qbeg = nv4 >> 1;  qend = nv4; }

    const int4* __restrict__ v2c4 = reinterpret_cast<const int4*>(v2c);
    float4* __restrict__ o = reinterpret_cast<float4*>(out + (size_t)b * n_vertices);

    const int S = BLOCK_THREADS;
    int v = qbeg + threadIdx.x;
    while (v + S < qend) {
        const int4 c0 = v2c4[v];
        const int4 c1 = v2c4[v + S];
        float4 a0, a1;
        a0.x = srow[c0.x]; a0.y = srow[c0.y]; a0.z = srow[c0.z]; a0.w = srow[c0.w];
        a1.x = srow[c1.x]; a1.y = srow[c1.y]; a1.z = srow[c1.z]; a1.w = srow[c1.w];
        __stcs(&o[v],     a0);
        __stcs(&o[v + S], a1);
        v += 2 * S;
    }
    if (v < qend) {
        const int4 c = v2c4[v];
        float4 a;
        a.x = srow[c.x]; a.y = srow[c.y]; a.z = srow[c.z]; a.w = srow[c.w];
        __stcs(&o[v], a);
    }
    // scalar vertex tail (dead for 100000; full-row CTA or half 1 handles it)
    if (half_id != 0) {
        for (int t = (nv4 << 2) + threadIdx.x; t < n_vertices; t += BLOCK_THREADS) {
            out[(size_t)b * n_vertices + t] = srow[v2c[t]];
        }
    }
}

extern "C" void kernel_launch(void* const* d_in, const int* in_sizes, int n_in,
                              void* d_out, int out_size)
{
    const float* x   = (const float*)d_in[0];
    const int*   v2c = (const int*)  d_in[1];
    float*       out = (float*)d_out;

    const int n_vertices = in_sizes[1];                  // 100000
    const int batch      = out_size / n_vertices;        // 1024
    const int n_clusters = in_sizes[0] / batch;          // 25000

    const int row_bytes  = n_clusters * (int)sizeof(float);      // 100000
    const int smem_bytes = ((row_bytes + 15) & ~15) + 16;        // row + mbarrier

    static int slots = 0;
    if (slots == 0) {
        cudaFuncSetAttribute(graph_reverse_pool_kernel,
                             cudaFuncAttributeMaxDynamicSharedMemorySize,
                             smem_bytes);
        int dev = 0, sms = 148;
        cudaGetDevice(&dev);
        cudaDeviceGetAttribute(&sms, cudaDevAttrMultiProcessorCount, dev);
        slots = 2 * sms;                                 // 2 CTAs/SM
        if (slots <= 0) slots = 296;
    }

    // Grid = exact multiple of slots; split (G - batch) rows into halves.
    int k = (batch + slots - 1) / slots;                 // waves needed
    int G = slots * k;
    if (G > 2 * batch) G = 2 * batch;                    // can't split more than all rows
    int n_split = G - batch;                             // rows that get 2 CTAs
    int n_full  = batch - n_split;                       // rows with 1 CTA

    graph_reverse_pool_kernel<<<G, BLOCK_THREADS, smem_bytes>>>(
        x, v2c, out, batch, n_clusters, n_vertices, n_full);
}